// round 1
// baseline (speedup 1.0000x reference)
#include <cuda_runtime.h>
#include <math.h>

#define KK 3
#define NN 16384
#define MM 4096
#define DD 128
#define HH 64

// Scratch (device globals: allocation-free rule)
__device__ float g_fx[KK * NN * HH];   // [K][N][H]
__device__ float g_fz[KK * MM * HH];   // [K][M][H]
__device__ float g_sn[KK * NN];        // |fx|^2
__device__ float g_sm[KK * MM];        // |fz|^2

__device__ __forceinline__ float sp(float v) {
    // softplus, numerically stable
    return fmaxf(v, 0.0f) + log1pf(__expf(-fabsf(v)));
}

// ---------------- packed f32x2 helpers ----------------
__device__ __forceinline__ unsigned long long pk2(float a, float b) {
    unsigned long long r;
    asm("mov.b64 %0, {%1, %2};" : "=l"(r) : "f"(a), "f"(b));
    return r;
}
__device__ __forceinline__ void upk2(unsigned long long v, float& a, float& b) {
    asm("mov.b64 {%0, %1}, %2;" : "=f"(a), "=f"(b) : "l"(v));
}
__device__ __forceinline__ void fma2(unsigned long long& d, unsigned long long a, unsigned long long b) {
    asm("fma.rn.f32x2 %0, %1, %2, %0;" : "+l"(d) : "l"(a), "l"(b));
}

// =====================================================================
// Kernel A: phi MLP.  Block = 64 rows x all 64 hidden units, 256 threads
// (16x16), 4x4 micro-tile.  grid = (320, 3): tiles 0..255 -> x, 256..319 -> z
// =====================================================================
__global__ __launch_bounds__(256) void phi_kernel(
    const float* __restrict__ x, const float* __restrict__ z,
    const float* __restrict__ W1, const float* __restrict__ b1,
    const float* __restrict__ W2, const float* __restrict__ b2,
    const float* __restrict__ W3, const float* __restrict__ b3) {
    extern __shared__ float smem[];
    float* XT  = smem;           // [128][64]  x tile, transposed [d][row]
    float* W1T = smem + 8192;    // [128][64]  W1 transposed [d][h]
    float* W2T = smem + 16384;   // [64][64]   [h][g]
    float* W3T = smem + 20480;   // [64][64]   [g][f]
    float* H1T = smem + 24576;   // [64][64]   [h][row] (reused for h2)
    float* RED = smem + 28672;   // [64][16]   norm reduction

    const int t  = threadIdx.x;
    const int tx = t & 15, ty = t >> 4;
    const int k  = blockIdx.y;
    const int bx = blockIdx.x;
    const bool isx = (bx < NN / 64);
    const int r0 = (isx ? bx : bx - NN / 64) * 64;
    const float* src  = isx ? x : z;
    float* fdst = isx ? (g_fx + k * NN * HH) : (g_fz + k * MM * HH);
    float* sdst = isx ? (g_sn + k * NN)      : (g_sm + k * MM);

    // --- load weights (transposed) ---
    const float* W1k = W1 + k * HH * DD;
    for (int q = t; q < HH * DD / 4; q += 256) {          // 2048 float4
        int h = q >> 5, d4 = (q & 31) << 2;
        float4 v = *(const float4*)(W1k + h * DD + d4);
        W1T[(d4 + 0) * 64 + h] = v.x; W1T[(d4 + 1) * 64 + h] = v.y;
        W1T[(d4 + 2) * 64 + h] = v.z; W1T[(d4 + 3) * 64 + h] = v.w;
    }
    const float* W2k = W2 + k * HH * HH;
    const float* W3k = W3 + k * HH * HH;
    for (int q = t; q < HH * HH / 4; q += 256) {          // 1024 float4
        int g = q >> 4, h4 = (q & 15) << 2;
        float4 v2 = *(const float4*)(W2k + g * HH + h4);
        W2T[(h4 + 0) * 64 + g] = v2.x; W2T[(h4 + 1) * 64 + g] = v2.y;
        W2T[(h4 + 2) * 64 + g] = v2.z; W2T[(h4 + 3) * 64 + g] = v2.w;
        float4 v3 = *(const float4*)(W3k + g * HH + h4);
        W3T[(h4 + 0) * 64 + g] = v3.x; W3T[(h4 + 1) * 64 + g] = v3.y;
        W3T[(h4 + 2) * 64 + g] = v3.z; W3T[(h4 + 3) * 64 + g] = v3.w;
    }
    // --- load x tile transposed ---
    for (int q = t; q < 64 * DD / 4; q += 256) {          // 2048 float4
        int r = q >> 5, d4 = (q & 31) << 2;
        float4 v = *(const float4*)(src + (size_t)(r0 + r) * DD + d4);
        XT[(d4 + 0) * 64 + r] = v.x; XT[(d4 + 1) * 64 + r] = v.y;
        XT[(d4 + 2) * 64 + r] = v.z; XT[(d4 + 3) * 64 + r] = v.w;
    }
    __syncthreads();

    float acc[4][4];

    // ---- GEMM1: [64 rows x 128 d] @ [128 d x 64 h] ----
    #pragma unroll
    for (int i = 0; i < 4; i++)
        #pragma unroll
        for (int j = 0; j < 4; j++) acc[i][j] = 0.0f;

    #pragma unroll 4
    for (int d = 0; d < DD; ++d) {
        float4 a4 = *(const float4*)&XT[d * 64 + (ty << 2)];
        float4 b4 = *(const float4*)&W1T[d * 64 + (tx << 2)];
        float av[4] = {a4.x, a4.y, a4.z, a4.w};
        float bv[4] = {b4.x, b4.y, b4.z, b4.w};
        #pragma unroll
        for (int i = 0; i < 4; i++)
            #pragma unroll
            for (int j = 0; j < 4; j++)
                acc[i][j] = fmaf(av[i], bv[j], acc[i][j]);
    }
    {
        const float* b1k = b1 + k * HH;
        #pragma unroll
        for (int j = 0; j < 4; j++) {
            float bj = b1k[(tx << 2) + j];
            #pragma unroll
            for (int i = 0; i < 4; i++) {
                float v = sp(acc[i][j] + bj);
                H1T[((tx << 2) + j) * 64 + (ty << 2) + i] = v;
            }
        }
    }
    __syncthreads();

    // ---- GEMM2: over h=64 ----
    #pragma unroll
    for (int i = 0; i < 4; i++)
        #pragma unroll
        for (int j = 0; j < 4; j++) acc[i][j] = 0.0f;

    #pragma unroll 4
    for (int h = 0; h < HH; ++h) {
        float4 a4 = *(const float4*)&H1T[h * 64 + (ty << 2)];
        float4 b4 = *(const float4*)&W2T[h * 64 + (tx << 2)];
        float av[4] = {a4.x, a4.y, a4.z, a4.w};
        float bv[4] = {b4.x, b4.y, b4.z, b4.w};
        #pragma unroll
        for (int i = 0; i < 4; i++)
            #pragma unroll
            for (int j = 0; j < 4; j++)
                acc[i][j] = fmaf(av[i], bv[j], acc[i][j]);
    }
    __syncthreads();   // all H1T reads done before overwrite
    {
        const float* b2k = b2 + k * HH;
        #pragma unroll
        for (int j = 0; j < 4; j++) {
            float bj = b2k[(tx << 2) + j];
            #pragma unroll
            for (int i = 0; i < 4; i++) {
                float v = sp(acc[i][j] + bj);
                H1T[((tx << 2) + j) * 64 + (ty << 2) + i] = v;  // now h2
            }
        }
    }
    __syncthreads();

    // ---- GEMM3: over g=64 ----
    #pragma unroll
    for (int i = 0; i < 4; i++)
        #pragma unroll
        for (int j = 0; j < 4; j++) acc[i][j] = 0.0f;

    #pragma unroll 4
    for (int g = 0; g < HH; ++g) {
        float4 a4 = *(const float4*)&H1T[g * 64 + (ty << 2)];
        float4 b4 = *(const float4*)&W3T[g * 64 + (tx << 2)];
        float av[4] = {a4.x, a4.y, a4.z, a4.w};
        float bv[4] = {b4.x, b4.y, b4.z, b4.w};
        #pragma unroll
        for (int i = 0; i < 4; i++)
            #pragma unroll
            for (int j = 0; j < 4; j++)
                acc[i][j] = fmaf(av[i], bv[j], acc[i][j]);
    }
    {
        const float* b3k = b3 + k * HH;
        float fr[4][4];
        #pragma unroll
        for (int j = 0; j < 4; j++) {
            float bj = b3k[(tx << 2) + j];
            #pragma unroll
            for (int i = 0; i < 4; i++) fr[i][j] = acc[i][j] + bj;
        }
        #pragma unroll
        for (int i = 0; i < 4; i++) {
            int row = r0 + (ty << 2) + i;
            float4 v = make_float4(fr[i][0], fr[i][1], fr[i][2], fr[i][3]);
            *(float4*)&fdst[(size_t)row * HH + (tx << 2)] = v;
            RED[((ty << 2) + i) * 16 + tx] =
                fr[i][0] * fr[i][0] + fr[i][1] * fr[i][1] +
                fr[i][2] * fr[i][2] + fr[i][3] * fr[i][3];
        }
    }
    __syncthreads();
    if (t < 64) {
        float s = 0.0f;
        #pragma unroll
        for (int q = 0; q < 16; q++) s += RED[t * 16 + q];
        sdst[r0 + t] = s;
    }
}

// =====================================================================
// Kernel B: fused pairwise kernel.  128x128 output tile, 256 threads,
// 8x8 micro-tile with packed f32x2 FMAs; RBF epilogue fused.
// =====================================================================
__global__ __launch_bounds__(256, 1) void pair_kernel(
    const float* __restrict__ log_sigma, const float* __restrict__ kw,
    float* __restrict__ out) {
    extern __shared__ float smem[];
    float* As  = smem;           // [64 h][128 n], XOR-swizzled
    float* Bs  = smem + 8192;    // [64 h][128 m], XOR-swizzled
    float* snS = smem + 16384;   // [128]
    float* smS = smem + 16512;   // [128]

    const int t  = threadIdx.x;
    const int tx = t & 15, ty = t >> 4;
    const int m0 = blockIdx.x * 128;
    const int n0 = blockIdx.y * 128;

    // per-kernel scalars (K=3)
    float w0r = kw[0], w1r = kw[1], w2r = kw[2];
    float wmax = fmaxf(fmaxf(w0r, w1r), w2r);
    float ew0 = __expf(w0r - wmax), ew1 = __expf(w1r - wmax), ew2 = __expf(w2r - wmax);
    float winv = 1.0f / (ew0 + ew1 + ew2);
    float wk[3] = {ew0 * winv, ew1 * winv, ew2 * winv};
    float c1[3];
    #pragma unroll
    for (int k = 0; k < 3; k++)
        c1[k] = 0.5f * exp2f(-log_sigma[k] * 3.3219280948873623f);  // 1/(2*10^ls)

    unsigned long long res2[8][4];
    #pragma unroll
    for (int i = 0; i < 8; i++)
        #pragma unroll
        for (int jj = 0; jj < 4; jj++) res2[i][jj] = 0ull;

    for (int k = 0; k < KK; k++) {
        __syncthreads();   // previous epilogue done before overwriting tiles
        const float* fxk = g_fx + (size_t)k * NN * HH;
        const float* fzk = g_fz + (size_t)k * MM * HH;
        for (int q = t; q < 2048; q += 256) {
            int r = q >> 4, h4 = (q & 15) << 2;
            float4 v = *(const float4*)(fxk + (size_t)(n0 + r) * HH + h4);
            As[(h4 + 0) * 128 + (r ^ (((h4 + 0) & 15) << 3))] = v.x;
            As[(h4 + 1) * 128 + (r ^ (((h4 + 1) & 15) << 3))] = v.y;
            As[(h4 + 2) * 128 + (r ^ (((h4 + 2) & 15) << 3))] = v.z;
            As[(h4 + 3) * 128 + (r ^ (((h4 + 3) & 15) << 3))] = v.w;
            float4 u = *(const float4*)(fzk + (size_t)(m0 + r) * HH + h4);
            Bs[(h4 + 0) * 128 + (r ^ (((h4 + 0) & 15) << 3))] = u.x;
            Bs[(h4 + 1) * 128 + (r ^ (((h4 + 1) & 15) << 3))] = u.y;
            Bs[(h4 + 2) * 128 + (r ^ (((h4 + 2) & 15) << 3))] = u.z;
            Bs[(h4 + 3) * 128 + (r ^ (((h4 + 3) & 15) << 3))] = u.w;
        }
        if (t < 128) {
            snS[t] = g_sn[k * NN + n0 + t];
            smS[t] = g_sm[k * MM + m0 + t];
        }
        __syncthreads();

        unsigned long long acc2[8][4];
        #pragma unroll
        for (int i = 0; i < 8; i++)
            #pragma unroll
            for (int jj = 0; jj < 4; jj++) acc2[i][jj] = 0ull;

        #pragma unroll 4
        for (int d = 0; d < HH; ++d) {
            int sw = (d & 15) << 3;
            const float4* ap = (const float4*)&As[d * 128 + ((ty << 3) ^ sw)];
            float4 a0 = ap[0], a1 = ap[1];
            const ulonglong2* bp = (const ulonglong2*)&Bs[d * 128 + ((tx << 3) ^ sw)];
            ulonglong2 bl = bp[0], bh = bp[1];
            unsigned long long bb[4] = {bl.x, bl.y, bh.x, bh.y};
            float av[8] = {a0.x, a0.y, a0.z, a0.w, a1.x, a1.y, a1.z, a1.w};
            #pragma unroll
            for (int i = 0; i < 8; i++) {
                unsigned long long ad = pk2(av[i], av[i]);
                #pragma unroll
                for (int jj = 0; jj < 4; jj++) fma2(acc2[i][jj], ad, bb[jj]);
            }
        }

        // epilogue: res += w_k * exp(min(c1*(2*dot - sn - sm), 0))
        float c1k = c1[k];
        float c2k = 2.0f * c1k;
        unsigned long long wd = pk2(wk[k], wk[k]);
        #pragma unroll
        for (int i = 0; i < 8; i++) {
            float pn = c1k * snS[(ty << 3) + i];
            #pragma unroll
            for (int jj = 0; jj < 4; jj++) {
                float d0, d1;
                upk2(acc2[i][jj], d0, d1);
                float pm0 = c1k * smS[(tx << 3) + 2 * jj + 0];
                float pm1 = c1k * smS[(tx << 3) + 2 * jj + 1];
                float g0 = fminf(fmaf(c2k, d0, -(pn + pm0)), 0.0f);
                float g1 = fminf(fmaf(c2k, d1, -(pn + pm1)), 0.0f);
                unsigned long long e2 = pk2(__expf(g0), __expf(g1));
                fma2(res2[i][jj], wd, e2);
            }
        }
    }

    // store 8x8 per thread
    #pragma unroll
    for (int i = 0; i < 8; i++) {
        float v0, v1, v2, v3, v4, v5, v6, v7;
        upk2(res2[i][0], v0, v1);
        upk2(res2[i][1], v2, v3);
        upk2(res2[i][2], v4, v5);
        upk2(res2[i][3], v6, v7);
        float* o = out + (size_t)(n0 + (ty << 3) + i) * MM + m0 + (tx << 3);
        *(float4*)(o + 0) = make_float4(v0, v1, v2, v3);
        *(float4*)(o + 4) = make_float4(v4, v5, v6, v7);
    }
}

extern "C" void kernel_launch(void* const* d_in, const int* in_sizes, int n_in,
                              void* d_out, int out_size) {
    const float* x  = (const float*)d_in[0];
    const float* z  = (const float*)d_in[1];
    const float* W1 = (const float*)d_in[2];
    const float* b1 = (const float*)d_in[3];
    const float* W2 = (const float*)d_in[4];
    const float* b2 = (const float*)d_in[5];
    const float* W3 = (const float*)d_in[6];
    const float* b3 = (const float*)d_in[7];
    const float* ls = (const float*)d_in[8];
    const float* kw = (const float*)d_in[9];
    float* out = (float*)d_out;

    cudaFuncSetAttribute(phi_kernel, cudaFuncAttributeMaxDynamicSharedMemorySize, 29696 * 4);
    cudaFuncSetAttribute(pair_kernel, cudaFuncAttributeMaxDynamicSharedMemorySize, 16640 * 4);

    phi_kernel<<<dim3(320, 3), 256, 29696 * 4>>>(x, z, W1, b1, W2, b2, W3, b3);
    pair_kernel<<<dim3(MM / 128, NN / 128), 256, 16640 * 4>>>(ls, kw, out);
}

// round 3
// speedup vs baseline: 1.6711x; 1.6711x over previous
#include <cuda_runtime.h>
#include <cuda_bf16.h>
#include <math.h>
#include <stdint.h>

#define KK 3
#define NN 16384
#define MM 4096
#define DD 128
#define HH 64
#define KS 192   // split reduction dim: 3 x 64 bf16

// Scratch (device globals: allocation-free rule)
// fx is the mma-A side (n rows): layout [hi, hi, lo]
// fz is the mma-B side (m rows): layout [hi, lo, hi]
// dot = hi*hi + hi*lo + lo*hi  (lo*lo term ~2^-16, negligible)
__device__ __nv_bfloat16 g_fxh[KK * NN * KS];
__device__ __nv_bfloat16 g_fzh[KK * MM * KS];
__device__ float g_sn[KK * NN];   // |fx|^2 fp32
__device__ float g_sm[KK * MM];   // |fz|^2 fp32

__device__ __forceinline__ float sp(float v) {
    return fmaxf(v, 0.0f) + log1pf(__expf(-fabsf(v)));
}

// ======================= async / mma helpers (sm_80 PTX only) =======================
__device__ __forceinline__ uint32_t smem_u32_of(const void* p) {
    return (uint32_t)__cvta_generic_to_shared(p);
}
__device__ __forceinline__ void cp16(uint32_t dst, const void* src) {
    asm volatile("cp.async.cg.shared.global [%0], [%1], 16;" :: "r"(dst), "l"(src));
}
__device__ __forceinline__ void cp_commit() {
    asm volatile("cp.async.commit_group;" ::: "memory");
}
template <int N_>
__device__ __forceinline__ void cp_wait() {
    asm volatile("cp.async.wait_group %0;" :: "n"(N_) : "memory");
}
__device__ __forceinline__ void ldsm4(uint32_t* f, uint32_t addr) {
    asm volatile("ldmatrix.sync.aligned.m8n8.x4.shared.b16 {%0,%1,%2,%3}, [%4];"
                 : "=r"(f[0]), "=r"(f[1]), "=r"(f[2]), "=r"(f[3]) : "r"(addr));
}
__device__ __forceinline__ void mma_bf16(float* c, const uint32_t* a, uint32_t b0, uint32_t b1) {
    asm volatile(
        "mma.sync.aligned.m16n8k16.row.col.f32.bf16.bf16.f32 "
        "{%0,%1,%2,%3}, {%4,%5,%6,%7}, {%8,%9}, {%0,%1,%2,%3};"
        : "+f"(c[0]), "+f"(c[1]), "+f"(c[2]), "+f"(c[3])
        : "r"(a[0]), "r"(a[1]), "r"(a[2]), "r"(a[3]), "r"(b0), "r"(b1));
}

// =====================================================================
// Kernel A: phi MLP -> bf16 hi/lo split features + fp32 norms
// =====================================================================
__global__ __launch_bounds__(256) void phi_kernel(
    const float* __restrict__ x, const float* __restrict__ z,
    const float* __restrict__ W1, const float* __restrict__ b1,
    const float* __restrict__ W2, const float* __restrict__ b2,
    const float* __restrict__ W3, const float* __restrict__ b3) {
    extern __shared__ float smem[];
    float* XT  = smem;           // [128][64]
    float* W1T = smem + 8192;    // [128][64]
    float* W2T = smem + 16384;   // [64][64]
    float* W3T = smem + 20480;   // [64][64]
    float* H1T = smem + 24576;   // [64][64]
    float* RED = smem + 28672;   // [64][16]

    const int t  = threadIdx.x;
    const int tx = t & 15, ty = t >> 4;
    const int k  = blockIdx.y;
    const int bx = blockIdx.x;
    const bool isx = (bx < NN / 64);
    const int r0 = (isx ? bx : bx - NN / 64) * 64;
    const float* src = isx ? x : z;
    __nv_bfloat16* dsth = isx ? (g_fxh + (size_t)k * NN * KS)
                              : (g_fzh + (size_t)k * MM * KS);
    float* sdst = isx ? (g_sn + k * NN) : (g_sm + k * MM);

    const float* W1k = W1 + k * HH * DD;
    for (int q = t; q < HH * DD / 4; q += 256) {
        int h = q >> 5, d4 = (q & 31) << 2;
        float4 v = *(const float4*)(W1k + h * DD + d4);
        W1T[(d4 + 0) * 64 + h] = v.x; W1T[(d4 + 1) * 64 + h] = v.y;
        W1T[(d4 + 2) * 64 + h] = v.z; W1T[(d4 + 3) * 64 + h] = v.w;
    }
    const float* W2k = W2 + k * HH * HH;
    const float* W3k = W3 + k * HH * HH;
    for (int q = t; q < HH * HH / 4; q += 256) {
        int g = q >> 4, h4 = (q & 15) << 2;
        float4 v2 = *(const float4*)(W2k + g * HH + h4);
        W2T[(h4 + 0) * 64 + g] = v2.x; W2T[(h4 + 1) * 64 + g] = v2.y;
        W2T[(h4 + 2) * 64 + g] = v2.z; W2T[(h4 + 3) * 64 + g] = v2.w;
        float4 v3 = *(const float4*)(W3k + g * HH + h4);
        W3T[(h4 + 0) * 64 + g] = v3.x; W3T[(h4 + 1) * 64 + g] = v3.y;
        W3T[(h4 + 2) * 64 + g] = v3.z; W3T[(h4 + 3) * 64 + g] = v3.w;
    }
    for (int q = t; q < 64 * DD / 4; q += 256) {
        int r = q >> 5, d4 = (q & 31) << 2;
        float4 v = *(const float4*)(src + (size_t)(r0 + r) * DD + d4);
        XT[(d4 + 0) * 64 + r] = v.x; XT[(d4 + 1) * 64 + r] = v.y;
        XT[(d4 + 2) * 64 + r] = v.z; XT[(d4 + 3) * 64 + r] = v.w;
    }
    __syncthreads();

    float acc[4][4];
    #pragma unroll
    for (int i = 0; i < 4; i++)
        #pragma unroll
        for (int j = 0; j < 4; j++) acc[i][j] = 0.0f;

    #pragma unroll 4
    for (int d = 0; d < DD; ++d) {
        float4 a4 = *(const float4*)&XT[d * 64 + (ty << 2)];
        float4 b4 = *(const float4*)&W1T[d * 64 + (tx << 2)];
        float av[4] = {a4.x, a4.y, a4.z, a4.w};
        float bv[4] = {b4.x, b4.y, b4.z, b4.w};
        #pragma unroll
        for (int i = 0; i < 4; i++)
            #pragma unroll
            for (int j = 0; j < 4; j++)
                acc[i][j] = fmaf(av[i], bv[j], acc[i][j]);
    }
    {
        const float* b1k = b1 + k * HH;
        #pragma unroll
        for (int j = 0; j < 4; j++) {
            float bj = b1k[(tx << 2) + j];
            #pragma unroll
            for (int i = 0; i < 4; i++)
                H1T[((tx << 2) + j) * 64 + (ty << 2) + i] = sp(acc[i][j] + bj);
        }
    }
    __syncthreads();

    #pragma unroll
    for (int i = 0; i < 4; i++)
        #pragma unroll
        for (int j = 0; j < 4; j++) acc[i][j] = 0.0f;
    #pragma unroll 4
    for (int h = 0; h < HH; ++h) {
        float4 a4 = *(const float4*)&H1T[h * 64 + (ty << 2)];
        float4 b4 = *(const float4*)&W2T[h * 64 + (tx << 2)];
        float av[4] = {a4.x, a4.y, a4.z, a4.w};
        float bv[4] = {b4.x, b4.y, b4.z, b4.w};
        #pragma unroll
        for (int i = 0; i < 4; i++)
            #pragma unroll
            for (int j = 0; j < 4; j++)
                acc[i][j] = fmaf(av[i], bv[j], acc[i][j]);
    }
    __syncthreads();
    {
        const float* b2k = b2 + k * HH;
        #pragma unroll
        for (int j = 0; j < 4; j++) {
            float bj = b2k[(tx << 2) + j];
            #pragma unroll
            for (int i = 0; i < 4; i++)
                H1T[((tx << 2) + j) * 64 + (ty << 2) + i] = sp(acc[i][j] + bj);
        }
    }
    __syncthreads();

    #pragma unroll
    for (int i = 0; i < 4; i++)
        #pragma unroll
        for (int j = 0; j < 4; j++) acc[i][j] = 0.0f;
    #pragma unroll 4
    for (int g = 0; g < HH; ++g) {
        float4 a4 = *(const float4*)&H1T[g * 64 + (ty << 2)];
        float4 b4 = *(const float4*)&W3T[g * 64 + (tx << 2)];
        float av[4] = {a4.x, a4.y, a4.z, a4.w};
        float bv[4] = {b4.x, b4.y, b4.z, b4.w};
        #pragma unroll
        for (int i = 0; i < 4; i++)
            #pragma unroll
            for (int j = 0; j < 4; j++)
                acc[i][j] = fmaf(av[i], bv[j], acc[i][j]);
    }
    {
        const float* b3k = b3 + k * HH;
        #pragma unroll
        for (int i = 0; i < 4; i++) {
            int row = r0 + (ty << 2) + i;
            float fv[4];
            #pragma unroll
            for (int j = 0; j < 4; j++) fv[j] = acc[i][j] + b3k[(tx << 2) + j];

            __nv_bfloat16 h[4], l[4];
            #pragma unroll
            for (int j = 0; j < 4; j++) {
                h[j] = __float2bfloat16(fv[j]);
                l[j] = __float2bfloat16(fv[j] - __bfloat162float(h[j]));
            }
            __nv_bfloat162 hp0 = __halves2bfloat162(h[0], h[1]);
            __nv_bfloat162 hp1 = __halves2bfloat162(h[2], h[3]);
            __nv_bfloat162 lp0 = __halves2bfloat162(l[0], l[1]);
            __nv_bfloat162 lp1 = __halves2bfloat162(l[2], l[3]);

            __nv_bfloat16* rowp = dsth + (size_t)row * KS + (tx << 2);
            *(__nv_bfloat162*)(rowp + 0) = hp0;
            *(__nv_bfloat162*)(rowp + 2) = hp1;
            if (isx) {  // A side (fx): [hi, hi, lo]
                *(__nv_bfloat162*)(rowp + 64)  = hp0;
                *(__nv_bfloat162*)(rowp + 66)  = hp1;
                *(__nv_bfloat162*)(rowp + 128) = lp0;
                *(__nv_bfloat162*)(rowp + 130) = lp1;
            } else {    // B side (fz): [hi, lo, hi]
                *(__nv_bfloat162*)(rowp + 64)  = lp0;
                *(__nv_bfloat162*)(rowp + 66)  = lp1;
                *(__nv_bfloat162*)(rowp + 128) = hp0;
                *(__nv_bfloat162*)(rowp + 130) = hp1;
            }
            RED[((ty << 2) + i) * 16 + tx] =
                fv[0] * fv[0] + fv[1] * fv[1] + fv[2] * fv[2] + fv[3] * fv[3];
        }
    }
    __syncthreads();
    if (t < 64) {
        float s = 0.0f;
        #pragma unroll
        for (int q = 0; q < 16; q++) s += RED[t * 16 + q];
        sdst[r0 + t] = s;
    }
}

// =====================================================================
// Kernel B: mma.sync bf16 pairwise GEMM + fused RBF epilogue.
// CTA tile: 128 n x 128 m.  8 warps: 4 over n (32 each), 2 over m (64 each).
// Per warp: 2 m16 blocks (n) x 8 n8 blocks (m), K=192 in 12 k16 steps.
// =====================================================================
// SMEM layout (bytes): snS[3*128 f32] smS[3*128 f32] then 2 stages of (A+B)
#define OFF_SN  0
#define OFF_SM  1536
#define OFF_ST  3072
#define ROWB    384                      // 192 bf16 per row
#define TILE_B  (128 * ROWB)             // 49152
#define STAGE_B (2 * TILE_B)             // 98304
#define SMEM_TOTAL (OFF_ST + 2 * STAGE_B)  // 199680

// load one 128x192 bf16 tile with chunk-XOR swizzle; 12 cp.async per thread
__device__ __forceinline__ void load_tile(const __nv_bfloat16* g, uint32_t sbase, int t) {
    int r = t >> 1;
    int ch0 = (t & 1) * 12;
    const char* gp = (const char*)(g + (size_t)r * KS) + ch0 * 16;
    uint32_t rb = sbase + r * ROWB;
    int r7 = r & 7;
    #pragma unroll
    for (int u = 0; u < 12; u++) {
        int c = ch0 + u;
        cp16(rb + (uint32_t)((c ^ r7) << 4), gp + u * 16);
    }
}

__global__ __launch_bounds__(256, 1) void pair_kernel(
    const float* __restrict__ log_sigma, const float* __restrict__ kw,
    float* __restrict__ out) {
    extern __shared__ char sm8[];
    const uint32_t sb = smem_u32_of(sm8);
    float* snS = (float*)(sm8 + OFF_SN);
    float* smS = (float*)(sm8 + OFF_SM);

    const int t = threadIdx.x;
    const int w = t >> 5, lane = t & 31;
    const int quad = lane >> 2, qid = lane & 3;
    const int wn = w & 3, wm = w >> 2;       // warp coords
    const int nb = wn * 32, mb = wm * 64;    // warp tile base within CTA tile
    const int m0 = blockIdx.x * 128;
    const int n0 = blockIdx.y * 128;

    // norms into smem
    for (int q = t; q < 3 * 128; q += 256) {
        snS[q] = g_sn[(q >> 7) * NN + n0 + (q & 127)];
        smS[q] = g_sm[(q >> 7) * MM + m0 + (q & 127)];
    }

    // per-kernel scalars
    float w0r = kw[0], w1r = kw[1], w2r = kw[2];
    float wmax = fmaxf(fmaxf(w0r, w1r), w2r);
    float ew0 = __expf(w0r - wmax), ew1 = __expf(w1r - wmax), ew2 = __expf(w2r - wmax);
    float winv = 1.0f / (ew0 + ew1 + ew2);
    float wk[3] = {ew0 * winv, ew1 * winv, ew2 * winv};
    float c1[3];
    #pragma unroll
    for (int k = 0; k < 3; k++)
        c1[k] = 0.5f * exp2f(-log_sigma[k] * 3.3219280948873623f);

    // prefetch k=0
    load_tile(g_fxh + (size_t)n0 * KS, sb + OFF_ST, t);
    load_tile(g_fzh + (size_t)m0 * KS, sb + OFF_ST + TILE_B, t);
    cp_commit();

    float res[2][8][4];
    #pragma unroll
    for (int mi = 0; mi < 2; mi++)
        #pragma unroll
        for (int nj = 0; nj < 8; nj++)
            #pragma unroll
            for (int r = 0; r < 4; r++) res[mi][nj][r] = 0.0f;

    // precompute per-lane ldmatrix row bases
    // A (fx): row = nb + mi*16 + (lane&15), chunk = 2*ks + (lane>>4)
    const int a_row = nb + (lane & 15);
    const int a_cb  = lane >> 4;
    // B (fz): row = mb + nj2*16 + ((lane>>4)<<3) + (lane&7), chunk = 2*ks + ((lane>>3)&1)
    const int b_row = mb + ((lane >> 4) << 3) + (lane & 7);
    const int b_cb  = (lane >> 3) & 1;

    #pragma unroll
    for (int k = 0; k < KK; k++) {
        if (k + 1 < KK) {
            load_tile(g_fxh + ((size_t)(k + 1) * NN + n0) * KS,
                      sb + OFF_ST + ((k + 1) & 1) * STAGE_B, t);
            load_tile(g_fzh + ((size_t)(k + 1) * MM + m0) * KS,
                      sb + OFF_ST + ((k + 1) & 1) * STAGE_B + TILE_B, t);
            cp_commit();
            cp_wait<1>();
        } else {
            cp_wait<0>();
        }
        __syncthreads();

        const uint32_t a_base = sb + OFF_ST + (uint32_t)(k & 1) * STAGE_B;
        const uint32_t b_base = a_base + TILE_B;

        float acc[2][8][4];
        #pragma unroll
        for (int mi = 0; mi < 2; mi++)
            #pragma unroll
            for (int nj = 0; nj < 8; nj++)
                #pragma unroll
                for (int r = 0; r < 4; r++) acc[mi][nj][r] = 0.0f;

        #pragma unroll 2
        for (int ks = 0; ks < 12; ks++) {
            uint32_t af[2][4];
            #pragma unroll
            for (int mi = 0; mi < 2; mi++) {
                int row = a_row + mi * 16;
                int c = (2 * ks + a_cb) ^ (row & 7);
                ldsm4(af[mi], a_base + row * ROWB + (c << 4));
            }
            uint32_t bf[4][4];
            #pragma unroll
            for (int nj2 = 0; nj2 < 4; nj2++) {
                int row = b_row + nj2 * 16;
                int c = (2 * ks + b_cb) ^ (row & 7);
                ldsm4(bf[nj2], b_base + row * ROWB + (c << 4));
            }
            #pragma unroll
            for (int mi = 0; mi < 2; mi++)
                #pragma unroll
                for (int nj2 = 0; nj2 < 4; nj2++) {
                    mma_bf16(acc[mi][2 * nj2 + 0], af[mi], bf[nj2][0], bf[nj2][1]);
                    mma_bf16(acc[mi][2 * nj2 + 1], af[mi], bf[nj2][2], bf[nj2][3]);
                }
        }

        // fused RBF epilogue for kernel k
        {
            float c1k = c1[k], c2k = 2.0f * c1k, wkk = wk[k];
            float pn[2][2];
            #pragma unroll
            for (int mi = 0; mi < 2; mi++) {
                pn[mi][0] = c1k * snS[k * 128 + nb + mi * 16 + quad];
                pn[mi][1] = c1k * snS[k * 128 + nb + mi * 16 + quad + 8];
            }
            #pragma unroll
            for (int nj = 0; nj < 8; nj++) {
                float2 pm2 = *(float2*)&smS[k * 128 + mb + nj * 8 + 2 * qid];
                float pm0 = c1k * pm2.x, pm1 = c1k * pm2.y;
                #pragma unroll
                for (int mi = 0; mi < 2; mi++) {
                    float g0 = fminf(fmaf(c2k, acc[mi][nj][0], -(pn[mi][0] + pm0)), 0.0f);
                    float g1 = fminf(fmaf(c2k, acc[mi][nj][1], -(pn[mi][0] + pm1)), 0.0f);
                    float g2 = fminf(fmaf(c2k, acc[mi][nj][2], -(pn[mi][1] + pm0)), 0.0f);
                    float g3 = fminf(fmaf(c2k, acc[mi][nj][3], -(pn[mi][1] + pm1)), 0.0f);
                    res[mi][nj][0] = fmaf(wkk, __expf(g0), res[mi][nj][0]);
                    res[mi][nj][1] = fmaf(wkk, __expf(g1), res[mi][nj][1]);
                    res[mi][nj][2] = fmaf(wkk, __expf(g2), res[mi][nj][2]);
                    res[mi][nj][3] = fmaf(wkk, __expf(g3), res[mi][nj][3]);
                }
            }
        }
        __syncthreads();   // all reads of this stage done before it is overwritten
    }

    // store: D rows = n, cols = m (contiguous float2 along m)
    #pragma unroll
    for (int mi = 0; mi < 2; mi++) {
        int nrow = n0 + nb + mi * 16 + quad;
        #pragma unroll
        for (int nj = 0; nj < 8; nj++) {
            float* p0 = out + (size_t)nrow * MM + m0 + mb + nj * 8 + 2 * qid;
            *(float2*)p0 = make_float2(res[mi][nj][0], res[mi][nj][1]);
            float* p1 = p0 + (size_t)8 * MM;
            *(float2*)p1 = make_float2(res[mi][nj][2], res[mi][nj][3]);
        }
    }
}

extern "C" void kernel_launch(void* const* d_in, const int* in_sizes, int n_in,
                              void* d_out, int out_size) {
    const float* x  = (const float*)d_in[0];
    const float* z  = (const float*)d_in[1];
    const float* W1 = (const float*)d_in[2];
    const float* b1 = (const float*)d_in[3];
    const float* W2 = (const float*)d_in[4];
    const float* b2 = (const float*)d_in[5];
    const float* W3 = (const float*)d_in[6];
    const float* b3 = (const float*)d_in[7];
    const float* ls = (const float*)d_in[8];
    const float* kwp = (const float*)d_in[9];
    float* out = (float*)d_out;

    cudaFuncSetAttribute(phi_kernel, cudaFuncAttributeMaxDynamicSharedMemorySize, 29696 * 4);
    cudaFuncSetAttribute(pair_kernel, cudaFuncAttributeMaxDynamicSharedMemorySize, SMEM_TOTAL);

    phi_kernel<<<dim3(320, 3), 256, 29696 * 4>>>(x, z, W1, b1, W2, b2, W3, b3);
    pair_kernel<<<dim3(MM / 128, NN / 128), 256, SMEM_TOTAL>>>(ls, kwp, out);
}

// round 4
// speedup vs baseline: 1.8588x; 1.1123x over previous
#include <cuda_runtime.h>
#include <cuda_bf16.h>
#include <math.h>
#include <stdint.h>

#define KK 3
#define NN 16384
#define MM 4096
#define DD 128
#define HH 64
#define KS 192   // split reduction dim: 3 x 64 bf16

// Scratch (device globals: allocation-free rule)
// fx = mma-A side (n rows): [hi, hi, lo]; fz = mma-B side (m rows): [hi, lo, hi]
// dot = hi*hi + hi*lo + lo*hi
__device__ __nv_bfloat16 g_fxh[KK * NN * KS];
__device__ __nv_bfloat16 g_fzh[KK * MM * KS];
__device__ float g_sn[KK * NN];
__device__ float g_sm[KK * MM];

__device__ __forceinline__ float sp(float v) {
    return fmaxf(v, 0.0f) + log1pf(__expf(-fabsf(v)));
}

// ======================= async / mma helpers (sm_80 PTX only) =======================
__device__ __forceinline__ uint32_t smem_u32_of(const void* p) {
    return (uint32_t)__cvta_generic_to_shared(p);
}
__device__ __forceinline__ void cp16(uint32_t dst, const void* src) {
    asm volatile("cp.async.cg.shared.global [%0], [%1], 16;" :: "r"(dst), "l"(src));
}
__device__ __forceinline__ void cp_commit() {
    asm volatile("cp.async.commit_group;" ::: "memory");
}
template <int N_>
__device__ __forceinline__ void cp_wait() {
    asm volatile("cp.async.wait_group %0;" :: "n"(N_) : "memory");
}
__device__ __forceinline__ void ldsm4(uint32_t* f, uint32_t addr) {
    asm volatile("ldmatrix.sync.aligned.m8n8.x4.shared.b16 {%0,%1,%2,%3}, [%4];"
                 : "=r"(f[0]), "=r"(f[1]), "=r"(f[2]), "=r"(f[3]) : "r"(addr));
}
__device__ __forceinline__ void mma_bf16(float* c, const uint32_t* a, uint32_t b0, uint32_t b1) {
    asm volatile(
        "mma.sync.aligned.m16n8k16.row.col.f32.bf16.bf16.f32 "
        "{%0,%1,%2,%3}, {%4,%5,%6,%7}, {%8,%9}, {%0,%1,%2,%3};"
        : "+f"(c[0]), "+f"(c[1]), "+f"(c[2]), "+f"(c[3])
        : "r"(a[0]), "r"(a[1]), "r"(a[2]), "r"(a[3]), "r"(b0), "r"(b1));
}

// =====================================================================
// Kernel A: phi MLP -> bf16 hi/lo split features + fp32 norms (unchanged)
// =====================================================================
__global__ __launch_bounds__(256) void phi_kernel(
    const float* __restrict__ x, const float* __restrict__ z,
    const float* __restrict__ W1, const float* __restrict__ b1,
    const float* __restrict__ W2, const float* __restrict__ b2,
    const float* __restrict__ W3, const float* __restrict__ b3) {
    extern __shared__ float smem[];
    float* XT  = smem;           // [128][64]
    float* W1T = smem + 8192;    // [128][64]
    float* W2T = smem + 16384;   // [64][64]
    float* W3T = smem + 20480;   // [64][64]
    float* H1T = smem + 24576;   // [64][64]
    float* RED = smem + 28672;   // [64][16]

    const int t  = threadIdx.x;
    const int tx = t & 15, ty = t >> 4;
    const int k  = blockIdx.y;
    const int bx = blockIdx.x;
    const bool isx = (bx < NN / 64);
    const int r0 = (isx ? bx : bx - NN / 64) * 64;
    const float* src = isx ? x : z;
    __nv_bfloat16* dsth = isx ? (g_fxh + (size_t)k * NN * KS)
                              : (g_fzh + (size_t)k * MM * KS);
    float* sdst = isx ? (g_sn + k * NN) : (g_sm + k * MM);

    const float* W1k = W1 + k * HH * DD;
    for (int q = t; q < HH * DD / 4; q += 256) {
        int h = q >> 5, d4 = (q & 31) << 2;
        float4 v = *(const float4*)(W1k + h * DD + d4);
        W1T[(d4 + 0) * 64 + h] = v.x; W1T[(d4 + 1) * 64 + h] = v.y;
        W1T[(d4 + 2) * 64 + h] = v.z; W1T[(d4 + 3) * 64 + h] = v.w;
    }
    const float* W2k = W2 + k * HH * HH;
    const float* W3k = W3 + k * HH * HH;
    for (int q = t; q < HH * HH / 4; q += 256) {
        int g = q >> 4, h4 = (q & 15) << 2;
        float4 v2 = *(const float4*)(W2k + g * HH + h4);
        W2T[(h4 + 0) * 64 + g] = v2.x; W2T[(h4 + 1) * 64 + g] = v2.y;
        W2T[(h4 + 2) * 64 + g] = v2.z; W2T[(h4 + 3) * 64 + g] = v2.w;
        float4 v3 = *(const float4*)(W3k + g * HH + h4);
        W3T[(h4 + 0) * 64 + g] = v3.x; W3T[(h4 + 1) * 64 + g] = v3.y;
        W3T[(h4 + 2) * 64 + g] = v3.z; W3T[(h4 + 3) * 64 + g] = v3.w;
    }
    for (int q = t; q < 64 * DD / 4; q += 256) {
        int r = q >> 5, d4 = (q & 31) << 2;
        float4 v = *(const float4*)(src + (size_t)(r0 + r) * DD + d4);
        XT[(d4 + 0) * 64 + r] = v.x; XT[(d4 + 1) * 64 + r] = v.y;
        XT[(d4 + 2) * 64 + r] = v.z; XT[(d4 + 3) * 64 + r] = v.w;
    }
    __syncthreads();

    float acc[4][4];
    #pragma unroll
    for (int i = 0; i < 4; i++)
        #pragma unroll
        for (int j = 0; j < 4; j++) acc[i][j] = 0.0f;

    #pragma unroll 4
    for (int d = 0; d < DD; ++d) {
        float4 a4 = *(const float4*)&XT[d * 64 + (ty << 2)];
        float4 b4 = *(const float4*)&W1T[d * 64 + (tx << 2)];
        float av[4] = {a4.x, a4.y, a4.z, a4.w};
        float bv[4] = {b4.x, b4.y, b4.z, b4.w};
        #pragma unroll
        for (int i = 0; i < 4; i++)
            #pragma unroll
            for (int j = 0; j < 4; j++)
                acc[i][j] = fmaf(av[i], bv[j], acc[i][j]);
    }
    {
        const float* b1k = b1 + k * HH;
        #pragma unroll
        for (int j = 0; j < 4; j++) {
            float bj = b1k[(tx << 2) + j];
            #pragma unroll
            for (int i = 0; i < 4; i++)
                H1T[((tx << 2) + j) * 64 + (ty << 2) + i] = sp(acc[i][j] + bj);
        }
    }
    __syncthreads();

    #pragma unroll
    for (int i = 0; i < 4; i++)
        #pragma unroll
        for (int j = 0; j < 4; j++) acc[i][j] = 0.0f;
    #pragma unroll 4
    for (int h = 0; h < HH; ++h) {
        float4 a4 = *(const float4*)&H1T[h * 64 + (ty << 2)];
        float4 b4 = *(const float4*)&W2T[h * 64 + (tx << 2)];
        float av[4] = {a4.x, a4.y, a4.z, a4.w};
        float bv[4] = {b4.x, b4.y, b4.z, b4.w};
        #pragma unroll
        for (int i = 0; i < 4; i++)
            #pragma unroll
            for (int j = 0; j < 4; j++)
                acc[i][j] = fmaf(av[i], bv[j], acc[i][j]);
    }
    __syncthreads();
    {
        const float* b2k = b2 + k * HH;
        #pragma unroll
        for (int j = 0; j < 4; j++) {
            float bj = b2k[(tx << 2) + j];
            #pragma unroll
            for (int i = 0; i < 4; i++)
                H1T[((tx << 2) + j) * 64 + (ty << 2) + i] = sp(acc[i][j] + bj);
        }
    }
    __syncthreads();

    #pragma unroll
    for (int i = 0; i < 4; i++)
        #pragma unroll
        for (int j = 0; j < 4; j++) acc[i][j] = 0.0f;
    #pragma unroll 4
    for (int g = 0; g < HH; ++g) {
        float4 a4 = *(const float4*)&H1T[g * 64 + (ty << 2)];
        float4 b4 = *(const float4*)&W3T[g * 64 + (tx << 2)];
        float av[4] = {a4.x, a4.y, a4.z, a4.w};
        float bv[4] = {b4.x, b4.y, b4.z, b4.w};
        #pragma unroll
        for (int i = 0; i < 4; i++)
            #pragma unroll
            for (int j = 0; j < 4; j++)
                acc[i][j] = fmaf(av[i], bv[j], acc[i][j]);
    }
    {
        const float* b3k = b3 + k * HH;
        #pragma unroll
        for (int i = 0; i < 4; i++) {
            int row = r0 + (ty << 2) + i;
            float fv[4];
            #pragma unroll
            for (int j = 0; j < 4; j++) fv[j] = acc[i][j] + b3k[(tx << 2) + j];

            __nv_bfloat16 h[4], l[4];
            #pragma unroll
            for (int j = 0; j < 4; j++) {
                h[j] = __float2bfloat16(fv[j]);
                l[j] = __float2bfloat16(fv[j] - __bfloat162float(h[j]));
            }
            __nv_bfloat162 hp0 = __halves2bfloat162(h[0], h[1]);
            __nv_bfloat162 hp1 = __halves2bfloat162(h[2], h[3]);
            __nv_bfloat162 lp0 = __halves2bfloat162(l[0], l[1]);
            __nv_bfloat162 lp1 = __halves2bfloat162(l[2], l[3]);

            __nv_bfloat16* rowp = dsth + (size_t)row * KS + (tx << 2);
            *(__nv_bfloat162*)(rowp + 0) = hp0;
            *(__nv_bfloat162*)(rowp + 2) = hp1;
            if (isx) {  // A side (fx): [hi, hi, lo]
                *(__nv_bfloat162*)(rowp + 64)  = hp0;
                *(__nv_bfloat162*)(rowp + 66)  = hp1;
                *(__nv_bfloat162*)(rowp + 128) = lp0;
                *(__nv_bfloat162*)(rowp + 130) = lp1;
            } else {    // B side (fz): [hi, lo, hi]
                *(__nv_bfloat162*)(rowp + 64)  = lp0;
                *(__nv_bfloat162*)(rowp + 66)  = lp1;
                *(__nv_bfloat162*)(rowp + 128) = hp0;
                *(__nv_bfloat162*)(rowp + 130) = hp1;
            }
            RED[((ty << 2) + i) * 16 + tx] =
                fv[0] * fv[0] + fv[1] * fv[1] + fv[2] * fv[2] + fv[3] * fv[3];
        }
    }
    __syncthreads();
    if (t < 64) {
        float s = 0.0f;
        #pragma unroll
        for (int q = 0; q < 16; q++) s += RED[t * 16 + q];
        sdst[r0 + t] = s;
    }
}

// =====================================================================
// Kernel B: mma.sync bf16 pairwise GEMM + fused RBF epilogue.
// CTA tile: 128 n x 128 m.  512 threads / 16 warps: 4 over n x 4 over m,
// warp tile 32n x 32m -> res 32 + acc 32 regs per thread (no spills).
// =====================================================================
#define OFF_SN  0
#define OFF_SM  1536
#define OFF_ST  3072
#define ROWB    384                      // 192 bf16 per row
#define TILE_B  (128 * ROWB)             // 49152
#define STAGE_B (2 * TILE_B)             // 98304
#define SMEM_TOTAL (OFF_ST + 2 * STAGE_B)  // 199680

// load one 128x192 bf16 tile with chunk-XOR swizzle; 6 cp.async per thread (512 thr)
__device__ __forceinline__ void load_tile(const __nv_bfloat16* g, uint32_t sbase, int t) {
    int r = t >> 2;
    int ch0 = (t & 3) * 6;
    const char* gp = (const char*)(g + (size_t)r * KS) + ch0 * 16;
    uint32_t rb = sbase + r * ROWB;
    int r7 = r & 7;
    #pragma unroll
    for (int u = 0; u < 6; u++) {
        int c = ch0 + u;
        cp16(rb + (uint32_t)((c ^ r7) << 4), gp + u * 16);
    }
}

__global__ __launch_bounds__(512, 1) void pair_kernel(
    const float* __restrict__ log_sigma, const float* __restrict__ kw,
    float* __restrict__ out) {
    extern __shared__ char sm8[];
    const uint32_t sb = smem_u32_of(sm8);
    float* snS = (float*)(sm8 + OFF_SN);
    float* smS = (float*)(sm8 + OFF_SM);

    const int t = threadIdx.x;
    const int w = t >> 5, lane = t & 31;
    const int quad = lane >> 2, qid = lane & 3;
    const int wn = w & 3, wm = w >> 2;       // 4 x 4 warp grid
    const int nb = wn * 32, mb = wm * 32;
    const int m0 = blockIdx.x * 128;
    const int n0 = blockIdx.y * 128;

    for (int q = t; q < 3 * 128; q += 512) {
        snS[q] = g_sn[(q >> 7) * NN + n0 + (q & 127)];
        smS[q] = g_sm[(q >> 7) * MM + m0 + (q & 127)];
    }

    float w0r = kw[0], w1r = kw[1], w2r = kw[2];
    float wmax = fmaxf(fmaxf(w0r, w1r), w2r);
    float ew0 = __expf(w0r - wmax), ew1 = __expf(w1r - wmax), ew2 = __expf(w2r - wmax);
    float winv = 1.0f / (ew0 + ew1 + ew2);
    float wk[3] = {ew0 * winv, ew1 * winv, ew2 * winv};
    float c1[3];
    #pragma unroll
    for (int k = 0; k < 3; k++)
        c1[k] = 0.5f * exp2f(-log_sigma[k] * 3.3219280948873623f);

    // prefetch k=0
    load_tile(g_fxh + (size_t)n0 * KS, sb + OFF_ST, t);
    load_tile(g_fzh + (size_t)m0 * KS, sb + OFF_ST + TILE_B, t);
    cp_commit();

    float res[2][4][4];
    #pragma unroll
    for (int mi = 0; mi < 2; mi++)
        #pragma unroll
        for (int nj = 0; nj < 4; nj++)
            #pragma unroll
            for (int r = 0; r < 4; r++) res[mi][nj][r] = 0.0f;

    // ldmatrix per-lane bases
    const int a_row = nb + (lane & 15);
    const int a_cb  = lane >> 4;
    const int b_row = mb + ((lane >> 4) << 3) + (lane & 7);
    const int b_cb  = (lane >> 3) & 1;

    #pragma unroll
    for (int k = 0; k < KK; k++) {
        if (k + 1 < KK) {
            load_tile(g_fxh + ((size_t)(k + 1) * NN + n0) * KS,
                      sb + OFF_ST + ((k + 1) & 1) * STAGE_B, t);
            load_tile(g_fzh + ((size_t)(k + 1) * MM + m0) * KS,
                      sb + OFF_ST + ((k + 1) & 1) * STAGE_B + TILE_B, t);
            cp_commit();
            cp_wait<1>();
        } else {
            cp_wait<0>();
        }
        __syncthreads();

        const uint32_t a_base = sb + OFF_ST + (uint32_t)(k & 1) * STAGE_B;
        const uint32_t b_base = a_base + TILE_B;

        float acc[2][4][4];
        #pragma unroll
        for (int mi = 0; mi < 2; mi++)
            #pragma unroll
            for (int nj = 0; nj < 4; nj++)
                #pragma unroll
                for (int r = 0; r < 4; r++) acc[mi][nj][r] = 0.0f;

        #pragma unroll 4
        for (int ks = 0; ks < 12; ks++) {
            uint32_t af[2][4];
            #pragma unroll
            for (int mi = 0; mi < 2; mi++) {
                int row = a_row + mi * 16;
                int c = (2 * ks + a_cb) ^ (row & 7);
                ldsm4(af[mi], a_base + row * ROWB + (c << 4));
            }
            uint32_t bf[2][4];
            #pragma unroll
            for (int nj2 = 0; nj2 < 2; nj2++) {
                int row = b_row + nj2 * 16;
                int c = (2 * ks + b_cb) ^ (row & 7);
                ldsm4(bf[nj2], b_base + row * ROWB + (c << 4));
            }
            #pragma unroll
            for (int mi = 0; mi < 2; mi++)
                #pragma unroll
                for (int nj2 = 0; nj2 < 2; nj2++) {
                    mma_bf16(acc[mi][2 * nj2 + 0], af[mi], bf[nj2][0], bf[nj2][1]);
                    mma_bf16(acc[mi][2 * nj2 + 1], af[mi], bf[nj2][2], bf[nj2][3]);
                }
        }

        // fused RBF epilogue
        {
            float c1k = c1[k], c2k = 2.0f * c1k, wkk = wk[k];
            float pn[2][2];
            #pragma unroll
            for (int mi = 0; mi < 2; mi++) {
                pn[mi][0] = c1k * snS[k * 128 + nb + mi * 16 + quad];
                pn[mi][1] = c1k * snS[k * 128 + nb + mi * 16 + quad + 8];
            }
            #pragma unroll
            for (int nj = 0; nj < 4; nj++) {
                float2 pm2 = *(float2*)&smS[k * 128 + mb + nj * 8 + 2 * qid];
                float pm0 = c1k * pm2.x, pm1 = c1k * pm2.y;
                #pragma unroll
                for (int mi = 0; mi < 2; mi++) {
                    float g0 = fminf(fmaf(c2k, acc[mi][nj][0], -(pn[mi][0] + pm0)), 0.0f);
                    float g1 = fminf(fmaf(c2k, acc[mi][nj][1], -(pn[mi][0] + pm1)), 0.0f);
                    float g2 = fminf(fmaf(c2k, acc[mi][nj][2], -(pn[mi][1] + pm0)), 0.0f);
                    float g3 = fminf(fmaf(c2k, acc[mi][nj][3], -(pn[mi][1] + pm1)), 0.0f);
                    res[mi][nj][0] = fmaf(wkk, __expf(g0), res[mi][nj][0]);
                    res[mi][nj][1] = fmaf(wkk, __expf(g1), res[mi][nj][1]);
                    res[mi][nj][2] = fmaf(wkk, __expf(g2), res[mi][nj][2]);
                    res[mi][nj][3] = fmaf(wkk, __expf(g3), res[mi][nj][3]);
                }
            }
        }
        __syncthreads();
    }

    // store: rows = n, cols = m (contiguous float2 along m)
    #pragma unroll
    for (int mi = 0; mi < 2; mi++) {
        int nrow = n0 + nb + mi * 16 + quad;
        #pragma unroll
        for (int nj = 0; nj < 4; nj++) {
            float* p0 = out + (size_t)nrow * MM + m0 + mb + nj * 8 + 2 * qid;
            *(float2*)p0 = make_float2(res[mi][nj][0], res[mi][nj][1]);
            float* p1 = p0 + (size_t)8 * MM;
            *(float2*)p1 = make_float2(res[mi][nj][2], res[mi][nj][3]);
        }
    }
}

extern "C" void kernel_launch(void* const* d_in, const int* in_sizes, int n_in,
                              void* d_out, int out_size) {
    const float* x  = (const float*)d_in[0];
    const float* z  = (const float*)d_in[1];
    const float* W1 = (const float*)d_in[2];
    const float* b1 = (const float*)d_in[3];
    const float* W2 = (const float*)d_in[4];
    const float* b2 = (const float*)d_in[5];
    const float* W3 = (const float*)d_in[6];
    const float* b3 = (const float*)d_in[7];
    const float* ls = (const float*)d_in[8];
    const float* kwp = (const float*)d_in[9];
    float* out = (float*)d_out;

    cudaFuncSetAttribute(phi_kernel, cudaFuncAttributeMaxDynamicSharedMemorySize, 29696 * 4);
    cudaFuncSetAttribute(pair_kernel, cudaFuncAttributeMaxDynamicSharedMemorySize, SMEM_TOTAL);

    phi_kernel<<<dim3(320, 3), 256, 29696 * 4>>>(x, z, W1, b1, W2, b2, W3, b3);
    pair_kernel<<<dim3(MM / 128, NN / 128), 512, SMEM_TOTAL>>>(ls, kwp, out);
}